// round 13
// baseline (speedup 1.0000x reference)
#include <cuda_runtime.h>
#include <cuda_bf16.h>
#include <cuda_fp16.h>

#define N_NODES 100000
#define N_EDGES 1600000
#define IN_DIM  12
#define HID     128
#define OUT_DIM 13
#define WPB     8      // warps per block (layer0)
#define WPB_F   16     // warps per block (agg kernels)
#define SCAN_B  391    // ceil(N_NODES/256)
#define GRID_C  512    // persistent CSR kernel grid

// ---------------- scratch (static device globals; no allocation) ----------------
__device__ int      g_idx[2 * N_NODES + 1];        // rowstart | cursor
__device__ int      g_bsum[512];                   // scan block sums
__device__ int      g_csr_src[N_EDGES];
__device__ unsigned g_U16[(size_t)N_NODES * 64];   // h1 @ Wl1, packed half2
__device__ unsigned g_V16[(size_t)N_NODES * 64];   // h1 @ Wr1 + b1, packed half2
__device__ unsigned g_H2[(size_t)N_NODES * 64];    // h2, packed half2
__device__ unsigned g_Ah[(size_t)N_NODES * 64];    // h1 packed bf16x2 (hi)
__device__ unsigned g_Al[(size_t)N_NODES * 64];    // h1 packed bf16x2 (lo)
__device__ unsigned g_Wth[2 * 128 * 64];           // W1^T packed bf16x2 hi: [m][n][kpair]
__device__ unsigned g_Wtl[2 * 128 * 64];           // lo
__device__ unsigned g_W2th[32 * 64];               // W2cat^T packed half2 hi: [n][kpair]
__device__ unsigned g_W2tl[32 * 64];               // lo
__device__ float    g_u2[(size_t)N_NODES * 16];    // h2 @ Wl2 (13, pad 16 — pads zeroed)
__device__ float    g_v2[(size_t)N_NODES * 16];    // h2 @ Wr2 + b2
__device__ unsigned g_bar_count;
__device__ unsigned g_bar_sense;

// ---------------- helpers ----------------
__device__ __forceinline__ unsigned pack_hi(float x, float y) {
    __nv_bfloat16 bx = __float2bfloat16(x);
    __nv_bfloat16 by = __float2bfloat16(y);
    return ((unsigned)__bfloat16_as_ushort(by) << 16) | __bfloat16_as_ushort(bx);
}
__device__ __forceinline__ unsigned pack_lo(float x, float y) {
    float rx = x - __bfloat162float(__float2bfloat16(x));
    float ry = y - __bfloat162float(__float2bfloat16(y));
    __nv_bfloat16 bx = __float2bfloat16(rx);
    __nv_bfloat16 by = __float2bfloat16(ry);
    return ((unsigned)__bfloat16_as_ushort(by) << 16) | __bfloat16_as_ushort(bx);
}
__device__ __forceinline__ unsigned pack_hi16(float x, float y) {
    __half2 h = __floats2half2_rn(x, y);
    return *(unsigned*)&h;
}
__device__ __forceinline__ unsigned pack_lo16(float x, float y) {
    float rx = x - __half2float(__float2half_rn(x));
    float ry = y - __half2float(__float2half_rn(y));
    __half2 h = __floats2half2_rn(rx, ry);
    return *(unsigned*)&h;
}

#define MMA_BF16(d, a, b)                                                        \
    asm volatile(                                                                \
        "mma.sync.aligned.m16n8k16.row.col.f32.bf16.bf16.f32 "                   \
        "{%0,%1,%2,%3}, {%4,%5,%6,%7}, {%8,%9}, {%0,%1,%2,%3};\n"                \
        : "+f"((d)[0]), "+f"((d)[1]), "+f"((d)[2]), "+f"((d)[3])                 \
        : "r"((a)[0]), "r"((a)[1]), "r"((a)[2]), "r"((a)[3]),                    \
          "r"((b)[0]), "r"((b)[1]))

#define MMA_F16(d, a, b)                                                         \
    asm volatile(                                                                \
        "mma.sync.aligned.m16n8k16.row.col.f32.f16.f16.f32 "                     \
        "{%0,%1,%2,%3}, {%4,%5,%6,%7}, {%8,%9}, {%0,%1,%2,%3};\n"                \
        : "+f"((d)[0]), "+f"((d)[1]), "+f"((d)[2]), "+f"((d)[3])                 \
        : "r"((a)[0]), "r"((a)[1]), "r"((a)[2]), "r"((a)[3]),                    \
          "r"((b)[0]), "r"((b)[1]))

// ---------------- persistent CSR build + weight prep ----------------
__device__ __forceinline__ void gbar(unsigned* s_sense) {
    __syncthreads();
    if (threadIdx.x == 0) {
        unsigned s = *s_sense ^ 1u;
        __threadfence();
        if (atomicAdd(&g_bar_count, 1u) == GRID_C - 1u) {
            g_bar_count = 0u;
            __threadfence();
            atomicExch(&g_bar_sense, s);
        } else {
            while (atomicAdd(&g_bar_sense, 0u) != s) __nanosleep(64);
        }
        __threadfence();
        *s_sense = s;
    }
    __syncthreads();
}

__device__ __forceinline__ float w2cat(const float* Wl2, const float* Wr2, int k, int n) {
    if (n < OUT_DIM) return Wl2[k * OUT_DIM + n];
    if (n < 2 * OUT_DIM) return Wr2[k * OUT_DIM + (n - OUT_DIM)];
    return 0.f;
}

__global__ void __launch_bounds__(256, 8)
csr_coop_kernel(const int* __restrict__ ei,
                const float* __restrict__ Wl,
                const float* __restrict__ Wr,
                const float* __restrict__ Wl2,
                const float* __restrict__ Wr2) {
    __shared__ int sh[256];
    __shared__ int sh2[512];
    __shared__ unsigned s_sense;
    int tid = threadIdx.x, bid = blockIdx.x;
    int gt = bid * 256 + tid;
    const int GSTRIDE = GRID_C * 256;
    if (tid == 0) s_sense = 0u;

    // Phase Z: zero degree counters + prep W1 split-bf16 + prep W2cat^T split-fp16
    for (int i = gt; i < N_NODES; i += GSTRIDE) g_idx[i] = 0;
    if (gt == 0) g_idx[N_NODES] = N_EDGES;
    for (int i = gt; i < 2 * 128 * 64; i += GSTRIDE) {
        int m = i >> 13;
        int rem = i & 8191;
        int n = rem >> 6;
        int c = rem & 63;
        const float* __restrict__ W = m ? Wr : Wl;
        float w0 = W[(2 * c)     * HID + n];
        float w1 = W[(2 * c + 1) * HID + n];
        g_Wth[i] = pack_hi(w0, w1);
        g_Wtl[i] = pack_lo(w0, w1);
    }
    for (int i = gt; i < 32 * 64; i += GSTRIDE) {
        int n = i >> 6, c = i & 63;
        float w0 = w2cat(Wl2, Wr2, 2 * c, n);
        float w1 = w2cat(Wl2, Wr2, 2 * c + 1, n);
        g_W2th[i] = pack_hi16(w0, w1);
        g_W2tl[i] = pack_lo16(w0, w1);
    }
    gbar(&s_sense);                                   // 1

    // Phase H: histogram of dst degrees
    for (int e = gt; e < N_EDGES; e += GSTRIDE)
        atomicAdd(&g_idx[__ldg(&ei[N_EDGES + e])], 1);
    gbar(&s_sense);                                   // 2

    // Phase S1: per-tile inclusive scan
    int d = 0;
    if (bid < SCAN_B) {
        int i = bid * 256 + tid;
        d = (i < N_NODES) ? g_idx[i] : 0;
        sh[tid] = d;
        __syncthreads();
        #pragma unroll
        for (int off = 1; off < 256; off <<= 1) {
            int v = (tid >= off) ? sh[tid - off] : 0;
            __syncthreads();
            sh[tid] += v;
            __syncthreads();
        }
        if (tid == 255) g_bsum[bid] = sh[255];
    }
    gbar(&s_sense);                                   // 3

    // Phase S2: block 0 scans tile sums
    int v0 = 0, v1 = 0;
    if (bid == 0) {
        v0 = (tid < SCAN_B) ? g_bsum[tid] : 0;
        v1 = (tid + 256 < SCAN_B) ? g_bsum[tid + 256] : 0;
        sh2[tid] = v0; sh2[tid + 256] = v1;
        __syncthreads();
        #pragma unroll
        for (int off = 1; off < 512; off <<= 1) {
            int a0 = (tid >= off) ? sh2[tid - off] : 0;
            int a1 = (tid + 256 >= off) ? sh2[tid + 256 - off] : 0;
            __syncthreads();
            sh2[tid] += a0;
            sh2[tid + 256] += a1;
            __syncthreads();
        }
        if (tid < SCAN_B) g_bsum[tid] = sh2[tid] - v0;
        if (tid + 256 < SCAN_B) g_bsum[tid + 256] = sh2[tid + 256] - v1;
    }
    gbar(&s_sense);                                   // 4

    // Phase S3: rowstart + cursor
    if (bid < SCAN_B) {
        int i = bid * 256 + tid;
        int r = g_bsum[bid] + sh[tid] - d;
        if (i < N_NODES) {
            g_idx[i]               = r;
            g_idx[N_NODES + 1 + i] = r;
        }
    }
    gbar(&s_sense);                                   // 5

    // Phase SC: scatter edges into CSR
    for (int e = gt; e < N_EDGES; e += GSTRIDE) {
        int dst = __ldg(&ei[N_EDGES + e]);
        int pos = atomicAdd(&g_idx[N_NODES + 1 + dst], 1);
        g_csr_src[pos] = __ldg(&ei[e]);
    }
    gbar(&s_sense);                                   // 6 (even -> sense returns to 0)
}

// ---------------- layer 0: agg(x,12) + FC(12->128) + relu -> packed bf16 h1 ----------------
__global__ void layer0_kernel(const float* __restrict__ x,
                              const float* __restrict__ Wl,
                              const float* __restrict__ Wr,
                              const float* __restrict__ b) {
    __shared__ float sh[WPB][2 * IN_DIM];
    int w = threadIdx.x >> 5, lane = threadIdx.x & 31;
    int n = blockIdx.x * WPB + w;
    if (n >= N_NODES) return;

    int beg = g_idx[n], end = g_idx[n + 1];
    float acc = 0.f;
    if (lane < IN_DIM) {
        #pragma unroll 4
        for (int e = beg; e < end; e++) {
            int src = g_csr_src[e];
            acc += __ldg(&x[src * IN_DIM + lane]);
        }
    }
    int degn = end - beg;
    float cnt = (float)(degn > 0 ? degn : 1);
    if (lane < IN_DIM) {
        sh[w][lane]          = acc / cnt;
        sh[w][IN_DIM + lane] = __ldg(&x[n * IN_DIM + lane]);
    }
    __syncwarp();

    int j = 4 * lane;
    float4 a = *(const float4*)&b[j];
    #pragma unroll
    for (int k = 0; k < IN_DIM; k++) {
        float  m  = sh[w][k];
        float  xx = sh[w][IN_DIM + k];
        float4 wl = *(const float4*)&Wl[k * HID + j];
        float4 wr = *(const float4*)&Wr[k * HID + j];
        a.x += m * wl.x + xx * wr.x;
        a.y += m * wl.y + xx * wr.y;
        a.z += m * wl.z + xx * wr.z;
        a.w += m * wl.w + xx * wr.w;
    }
    a.x = fmaxf(a.x, 0.f); a.y = fmaxf(a.y, 0.f);
    a.z = fmaxf(a.z, 0.f); a.w = fmaxf(a.w, 0.f);

    size_t base = (size_t)n * 64 + 2 * lane;
    g_Ah[base]     = pack_hi(a.x, a.y);
    g_Ah[base + 1] = pack_hi(a.z, a.w);
    g_Al[base]     = pack_lo(a.x, a.y);
    g_Al[base + 1] = pack_lo(a.z, a.w);
}

// ---------------- tensor-core SGEMM: U(half)=h1@Wl1 (y=0), V(half)=h1@Wr1+b1 (y=1) ----------------
__global__ void sgemm_tc_kernel(const float* __restrict__ bias) {
    __shared__ unsigned As_h[64 * 20], As_l[64 * 20];
    __shared__ unsigned Bs_h[128 * 20], Bs_l[128 * 20];

    int tid = threadIdx.x, lane = tid & 31, wid = tid >> 5;
    int warp_m = wid >> 2, warp_n = wid & 3;
    int m_base = blockIdx.x * 64;
    int sel = blockIdx.y;
    const unsigned* __restrict__ Wt_h = g_Wth + sel * (128 * 64);
    const unsigned* __restrict__ Wt_l = g_Wtl + sel * (128 * 64);

    float acc[2][4][4];
    #pragma unroll
    for (int i = 0; i < 2; i++)
        #pragma unroll
        for (int jj = 0; jj < 4; jj++)
            acc[i][jj][0] = acc[i][jj][1] = acc[i][jj][2] = acc[i][jj][3] = 0.f;

    int ar = tid >> 2, ac4 = (tid & 3) * 4;
    int arow = m_base + ar; if (arow >= N_NODES) arow = N_NODES - 1;
    int bn = tid >> 1, bc8 = (tid & 1) * 8;

    for (int k0 = 0; k0 < 64; k0 += 16) {
        uint4 ah = *(const uint4*)&g_Ah[(size_t)arow * 64 + k0 + ac4];
        uint4 al = *(const uint4*)&g_Al[(size_t)arow * 64 + k0 + ac4];
        uint4 bh0 = *(const uint4*)&Wt_h[bn * 64 + k0 + bc8];
        uint4 bh1 = *(const uint4*)&Wt_h[bn * 64 + k0 + bc8 + 4];
        uint4 bl0 = *(const uint4*)&Wt_l[bn * 64 + k0 + bc8];
        uint4 bl1 = *(const uint4*)&Wt_l[bn * 64 + k0 + bc8 + 4];
        __syncthreads();
        *(uint4*)&As_h[ar * 20 + ac4] = ah;
        *(uint4*)&As_l[ar * 20 + ac4] = al;
        *(uint4*)&Bs_h[bn * 20 + bc8]     = bh0;
        *(uint4*)&Bs_h[bn * 20 + bc8 + 4] = bh1;
        *(uint4*)&Bs_l[bn * 20 + bc8]     = bl0;
        *(uint4*)&Bs_l[bn * 20 + bc8 + 4] = bl1;
        __syncthreads();

        #pragma unroll
        for (int ks = 0; ks < 2; ks++) {
            int cb = ks * 8 + (lane & 3);
            unsigned a_h[2][4], a_l[2][4];
            #pragma unroll
            for (int tm = 0; tm < 2; tm++) {
                int r0 = (warp_m * 32 + tm * 16 + (lane >> 2)) * 20 + cb;
                a_h[tm][0] = As_h[r0];            a_h[tm][1] = As_h[r0 + 8 * 20];
                a_h[tm][2] = As_h[r0 + 4];        a_h[tm][3] = As_h[r0 + 8 * 20 + 4];
                a_l[tm][0] = As_l[r0];            a_l[tm][1] = As_l[r0 + 8 * 20];
                a_l[tm][2] = As_l[r0 + 4];        a_l[tm][3] = As_l[r0 + 8 * 20 + 4];
            }
            unsigned b_h[4][2], b_l[4][2];
            #pragma unroll
            for (int tn = 0; tn < 4; tn++) {
                int q = (warp_n * 32 + tn * 8 + (lane >> 2)) * 20 + cb;
                b_h[tn][0] = Bs_h[q]; b_h[tn][1] = Bs_h[q + 4];
                b_l[tn][0] = Bs_l[q]; b_l[tn][1] = Bs_l[q + 4];
            }
            #pragma unroll
            for (int tm = 0; tm < 2; tm++)
                #pragma unroll
                for (int tn = 0; tn < 4; tn++) {
                    MMA_BF16(acc[tm][tn], a_h[tm], b_h[tn]);
                    MMA_BF16(acc[tm][tn], a_h[tm], b_l[tn]);
                    MMA_BF16(acc[tm][tn], a_l[tm], b_h[tn]);
                }
        }
    }

    unsigned* __restrict__ C16 = sel ? g_V16 : g_U16;
    #pragma unroll
    for (int tn = 0; tn < 4; tn++) {
        int col = warp_n * 32 + tn * 8 + 2 * (lane & 3);
        float bx = 0.f, by = 0.f;
        if (sel) { bx = __ldg(&bias[col]); by = __ldg(&bias[col + 1]); }
        #pragma unroll
        for (int tm = 0; tm < 2; tm++) {
            int row0 = m_base + warp_m * 32 + tm * 16 + (lane >> 2);
            if (row0 < N_NODES) {
                __half2 h = __floats2half2_rn(acc[tm][tn][0] + bx, acc[tm][tn][1] + by);
                C16[(size_t)row0 * 64 + col / 2] = *(unsigned*)&h;
            }
            int row1 = row0 + 8;
            if (row1 < N_NODES) {
                __half2 h = __floats2half2_rn(acc[tm][tn][2] + bx, acc[tm][tn][3] + by);
                C16[(size_t)row1 * 64 + col / 2] = *(unsigned*)&h;
            }
        }
    }
}

// ---------------- agg2: h2 = relu(mean(U16[nbrs]) + V16[n]) -> packed fp16 g_H2 ----------------
// Pure gather; 2 edges per warp-iteration; packed HADD2 accumulation,
// flushed to fp32 every 8 edges (4 iterations) to bound fp16 error chains.
__global__ void agg2_kernel() {
    int w = threadIdx.x >> 5, lane = threadIdx.x & 31;
    int n = blockIdx.x * WPB_F + w;
    if (n >= N_NODES) return;

    int beg = g_idx[n], end = g_idx[n + 1];
    int half = lane >> 4;
    int fl   = lane & 15;
    float acc[8];
    #pragma unroll
    for (int i = 0; i < 8; i++) acc[i] = 0.f;

    const __half2 z2 = __floats2half2_rn(0.f, 0.f);
    int e = beg + 2 * half - 2;                 // this lane's first edge minus stride
    for (int g = beg; g < end; g += 8) {        // 8-edge groups (4 iters of 2)
        __half2 h0 = z2, h1 = z2, h2 = z2, h3 = z2;
        int glim = g + 8 < end ? g + 8 : end;
        for (int ee = g + half; ee < glim; ee += 2) {
            int src = g_csr_src[ee];
            uint4 u = *(const uint4*)&g_U16[(size_t)src * 64 + 4 * fl];
            h0 = __hadd2(h0, *(const __half2*)&u.x);
            h1 = __hadd2(h1, *(const __half2*)&u.y);
            h2 = __hadd2(h2, *(const __half2*)&u.z);
            h3 = __hadd2(h3, *(const __half2*)&u.w);
        }
        float2 f;
        f = __half22float2(h0); acc[0] += f.x; acc[1] += f.y;
        f = __half22float2(h1); acc[2] += f.x; acc[3] += f.y;
        f = __half22float2(h2); acc[4] += f.x; acc[5] += f.y;
        f = __half22float2(h3); acc[6] += f.x; acc[7] += f.y;
    }
    (void)e;
    #pragma unroll
    for (int i = 0; i < 8; i++)
        acc[i] += __shfl_xor_sync(0xffffffffu, acc[i], 16);

    int degn = end - beg;
    float inv = 1.f / (float)(degn > 0 ? degn : 1);
    if (half == 0) {
        uint4 vv = *(const uint4*)&g_V16[(size_t)n * 64 + 4 * fl];
        float2 v0 = __half22float2(*(const __half2*)&vv.x);
        float2 v1 = __half22float2(*(const __half2*)&vv.y);
        float2 v2 = __half22float2(*(const __half2*)&vv.z);
        float2 v3 = __half22float2(*(const __half2*)&vv.w);
        uint4 o;
        o.x = pack_hi16(fmaxf(acc[0] * inv + v0.x, 0.f), fmaxf(acc[1] * inv + v0.y, 0.f));
        o.y = pack_hi16(fmaxf(acc[2] * inv + v1.x, 0.f), fmaxf(acc[3] * inv + v1.y, 0.f));
        o.z = pack_hi16(fmaxf(acc[4] * inv + v2.x, 0.f), fmaxf(acc[5] * inv + v2.y, 0.f));
        o.w = pack_hi16(fmaxf(acc[6] * inv + v3.x, 0.f), fmaxf(acc[7] * inv + v3.y, 0.f));
        *(uint4*)&g_H2[(size_t)n * 64 + 4 * fl] = o;
    }
}

// ---------------- gemm2_tc: [u2|v2|pads] = H2 @ W2cat  (M=64/block, N=32, K=128) ----------------
__global__ void __launch_bounds__(128)
gemm2_tc_kernel(const float* __restrict__ b2) {
    __shared__ unsigned As[64 * 68];       // h2 tile, stride 68 half2
    __shared__ unsigned Bs_h[32 * 66];     // W2cat^T hi, stride 66
    __shared__ unsigned Bs_l[32 * 66];

    int tid = threadIdx.x, lane = tid & 31, wid = tid >> 5;   // 4 warps
    int m_base = blockIdx.x * 64;

    // load A tile: 64 rows x 64 half2 (8 uint4 per thread)
    {
        int row = tid >> 1;
        int g_row = m_base + row; if (g_row >= N_NODES) g_row = N_NODES - 1;
        int cbase = (tid & 1) * 8;
        #pragma unroll
        for (int i = 0; i < 8; i++) {
            uint4 v = *(const uint4*)&g_H2[(size_t)g_row * 64 + (cbase + i) * 4];
            *(uint4*)&As[row * 68 + (cbase + i) * 4] = v;
        }
    }
    // load B tiles
    for (int i = tid; i < 32 * 64; i += 128) {
        int r = i >> 6, c = i & 63;
        Bs_h[r * 66 + c] = g_W2th[i];
        Bs_l[r * 66 + c] = g_W2tl[i];
    }
    __syncthreads();

    float acc[4][4];
    #pragma unroll
    for (int tn = 0; tn < 4; tn++)
        acc[tn][0] = acc[tn][1] = acc[tn][2] = acc[tn][3] = 0.f;

    #pragma unroll
    for (int ks = 0; ks < 8; ks++) {
        int cb = ks * 8 + (lane & 3);
        unsigned a[4];
        int r0 = (16 * wid + (lane >> 2)) * 68 + cb;
        a[0] = As[r0];           a[1] = As[r0 + 8 * 68];
        a[2] = As[r0 + 4];       a[3] = As[r0 + 8 * 68 + 4];
        #pragma unroll
        for (int tn = 0; tn < 4; tn++) {
            int q = (tn * 8 + (lane >> 2)) * 66 + cb;
            unsigned bh[2] = { Bs_h[q], Bs_h[q + 4] };
            unsigned bl[2] = { Bs_l[q], Bs_l[q + 4] };
            MMA_F16(acc[tn], a, bh);
            MMA_F16(acc[tn], a, bl);
        }
    }

    #pragma unroll
    for (int tn = 0; tn < 4; tn++) {
        int n0 = tn * 8 + 2 * (lane & 3);
        #pragma unroll
        for (int half = 0; half < 2; half++) {
            int node = m_base + 16 * wid + (lane >> 2) + 8 * half;
            if (node < N_NODES) {
                float va = acc[tn][2 * half], vb = acc[tn][2 * half + 1];
                #pragma unroll
                for (int p = 0; p < 2; p++) {
                    int nn = n0 + p;
                    float v = p ? vb : va;
                    if (nn < OUT_DIM) {
                        g_u2[(size_t)node * 16 + nn] = v;
                    } else if (nn < 2 * OUT_DIM) {
                        g_v2[(size_t)node * 16 + (nn - OUT_DIM)] = v + __ldg(&b2[nn - OUT_DIM]);
                    } else if (nn < 29) {
                        g_u2[(size_t)node * 16 + (nn - OUT_DIM)] = 0.f;  // u2 pads 13..15
                    }
                }
            }
        }
    }
}

// ---------------- final: out = hiermax(sigmoid(mean(u2[nbrs]) + v2[n])) ----------------
__global__ void aggF_kernel(const int* __restrict__ R, float* __restrict__ out) {
    __shared__ float s[WPB_F][OUT_DIM];
    int w = threadIdx.x >> 5, lane = threadIdx.x & 31;
    int n = blockIdx.x * WPB_F + w;
    if (n >= N_NODES) return;

    int beg = g_idx[n], end = g_idx[n + 1];
    int half = lane >> 4;
    int fl   = lane & 15;
    float acc = 0.f;
    #pragma unroll 4
    for (int e = beg; e < end; e += 2) {
        int ee = e + half;
        if (ee < end) {
            int src = g_csr_src[ee];
            acc += g_u2[(size_t)src * 16 + fl];
        }
    }
    acc += __shfl_xor_sync(0xffffffffu, acc, 16);

    int degn = end - beg;
    float inv = 1.f / (float)(degn > 0 ? degn : 1);
    if (lane < OUT_DIM) {
        float z = acc * inv + g_v2[(size_t)n * 16 + lane];
        s[w][lane] = 1.f / (1.f + expf(-z));
    }
    __syncwarp();
    if (lane < OUT_DIM) {
        float mx = 0.f;
        #pragma unroll
        for (int jj = 0; jj < OUT_DIM; jj++) {
            if (__ldg(&R[lane * OUT_DIM + jj])) mx = fmaxf(mx, s[w][jj]);
        }
        out[(size_t)n * OUT_DIM + lane] = mx;
    }
}

// ---------------- launch ----------------
extern "C" void kernel_launch(void* const* d_in, const int* in_sizes, int n_in,
                              void* d_out, int out_size) {
    const float* x   = (const float*)d_in[0];
    const float* Wl0 = (const float*)d_in[1];
    const float* Wr0 = (const float*)d_in[2];
    const float* b0  = (const float*)d_in[3];
    const float* Wl1 = (const float*)d_in[4];
    const float* Wr1 = (const float*)d_in[5];
    const float* b1  = (const float*)d_in[6];
    const float* Wl2 = (const float*)d_in[7];
    const float* Wr2 = (const float*)d_in[8];
    const float* b2  = (const float*)d_in[9];
    const int*   ei  = (const int*)d_in[10];
    const int*   R   = (const int*)d_in[11];
    float* out = (float*)d_out;
    (void)in_sizes; (void)n_in; (void)out_size;

    csr_coop_kernel<<<GRID_C, 256>>>(ei, Wl1, Wr1, Wl2, Wr2);      // launch 1

    int nb = (N_NODES + WPB - 1) / WPB;
    layer0_kernel<<<nb, WPB * 32>>>(x, Wl0, Wr0, b0);              // launch 2

    dim3 gg((N_NODES + 63) / 64, 2);
    sgemm_tc_kernel<<<gg, 256>>>(b1);                              // launch 3

    int nbf = (N_NODES + WPB_F - 1) / WPB_F;
    agg2_kernel<<<nbf, WPB_F * 32>>>();                            // launch 4 <- profiled

    gemm2_tc_kernel<<<(N_NODES + 63) / 64, 128>>>(b2);             // launch 5
    aggF_kernel<<<nbf, WPB_F * 32>>>(R, out);                      // launch 6
}

// round 14
// speedup vs baseline: 1.0918x; 1.0918x over previous
#include <cuda_runtime.h>
#include <cuda_bf16.h>
#include <cuda_fp16.h>

#define N_NODES 100000
#define N_EDGES 1600000
#define IN_DIM  12
#define HID     128
#define OUT_DIM 13
#define WPB     8      // warps per block (layer0)
#define WPB_F   16     // warps per block (agg kernels)
#define SCAN_B  391    // ceil(N_NODES/256)
#define GRID_C  512    // persistent CSR kernel grid

// ---------------- scratch (static device globals; no allocation) ----------------
__device__ int      g_idx[2 * N_NODES + 1];        // rowstart | cursor
__device__ int      g_bsum[512];                   // scan block sums
__device__ int      g_csr_src[N_EDGES];
__device__ unsigned g_U16[(size_t)N_NODES * 64];   // h1 @ Wl1, packed half2
__device__ unsigned g_V16[(size_t)N_NODES * 64];   // h1 @ Wr1 + b1, packed half2
__device__ unsigned g_H2[(size_t)N_NODES * 64];    // h2, packed half2
__device__ unsigned g_Ah[(size_t)N_NODES * 64];    // h1 packed bf16x2 (hi)
__device__ unsigned g_Al[(size_t)N_NODES * 64];    // h1 packed bf16x2 (lo)
__device__ unsigned g_Wth[2 * 128 * 64];           // W1^T packed bf16x2 hi: [m][n][kpair]
__device__ unsigned g_Wtl[2 * 128 * 64];           // lo
__device__ unsigned g_W2th[32 * 64];               // W2cat^T packed half2 hi: [n][kpair]
__device__ unsigned g_W2tl[32 * 64];               // lo
__device__ float    g_u2[(size_t)N_NODES * 16];    // h2 @ Wl2 (13, pad 16 — pads zeroed)
__device__ float    g_v2[(size_t)N_NODES * 16];    // h2 @ Wr2 + b2
__device__ unsigned g_bar_count;
__device__ unsigned g_bar_sense;

// ---------------- helpers ----------------
__device__ __forceinline__ unsigned pack_hi(float x, float y) {
    __nv_bfloat16 bx = __float2bfloat16(x);
    __nv_bfloat16 by = __float2bfloat16(y);
    return ((unsigned)__bfloat16_as_ushort(by) << 16) | __bfloat16_as_ushort(bx);
}
__device__ __forceinline__ unsigned pack_lo(float x, float y) {
    float rx = x - __bfloat162float(__float2bfloat16(x));
    float ry = y - __bfloat162float(__float2bfloat16(y));
    __nv_bfloat16 bx = __float2bfloat16(rx);
    __nv_bfloat16 by = __float2bfloat16(ry);
    return ((unsigned)__bfloat16_as_ushort(by) << 16) | __bfloat16_as_ushort(bx);
}
__device__ __forceinline__ unsigned pack_hi16(float x, float y) {
    __half2 h = __floats2half2_rn(x, y);
    return *(unsigned*)&h;
}
__device__ __forceinline__ unsigned pack_lo16(float x, float y) {
    float rx = x - __half2float(__float2half_rn(x));
    float ry = y - __half2float(__float2half_rn(y));
    __half2 h = __floats2half2_rn(rx, ry);
    return *(unsigned*)&h;
}

#define MMA_BF16(d, a, b)                                                        \
    asm volatile(                                                                \
        "mma.sync.aligned.m16n8k16.row.col.f32.bf16.bf16.f32 "                   \
        "{%0,%1,%2,%3}, {%4,%5,%6,%7}, {%8,%9}, {%0,%1,%2,%3};\n"                \
        : "+f"((d)[0]), "+f"((d)[1]), "+f"((d)[2]), "+f"((d)[3])                 \
        : "r"((a)[0]), "r"((a)[1]), "r"((a)[2]), "r"((a)[3]),                    \
          "r"((b)[0]), "r"((b)[1]))

#define MMA_F16(d, a, b)                                                         \
    asm volatile(                                                                \
        "mma.sync.aligned.m16n8k16.row.col.f32.f16.f16.f32 "                     \
        "{%0,%1,%2,%3}, {%4,%5,%6,%7}, {%8,%9}, {%0,%1,%2,%3};\n"                \
        : "+f"((d)[0]), "+f"((d)[1]), "+f"((d)[2]), "+f"((d)[3])                 \
        : "r"((a)[0]), "r"((a)[1]), "r"((a)[2]), "r"((a)[3]),                    \
          "r"((b)[0]), "r"((b)[1]))

// ---------------- persistent CSR build + weight prep ----------------
__device__ __forceinline__ void gbar(unsigned* s_sense) {
    __syncthreads();
    if (threadIdx.x == 0) {
        unsigned s = *s_sense ^ 1u;
        __threadfence();
        if (atomicAdd(&g_bar_count, 1u) == GRID_C - 1u) {
            g_bar_count = 0u;
            __threadfence();
            atomicExch(&g_bar_sense, s);
        } else {
            while (atomicAdd(&g_bar_sense, 0u) != s) __nanosleep(64);
        }
        __threadfence();
        *s_sense = s;
    }
    __syncthreads();
}

__device__ __forceinline__ float w2cat(const float* Wl2, const float* Wr2, int k, int n) {
    if (n < OUT_DIM) return Wl2[k * OUT_DIM + n];
    if (n < 2 * OUT_DIM) return Wr2[k * OUT_DIM + (n - OUT_DIM)];
    return 0.f;
}

__global__ void __launch_bounds__(256, 8)
csr_coop_kernel(const int* __restrict__ ei,
                const float* __restrict__ Wl,
                const float* __restrict__ Wr,
                const float* __restrict__ Wl2,
                const float* __restrict__ Wr2) {
    __shared__ int sh[256];
    __shared__ int sh2[512];
    __shared__ unsigned s_sense;
    int tid = threadIdx.x, bid = blockIdx.x;
    int gt = bid * 256 + tid;
    const int GSTRIDE = GRID_C * 256;
    if (tid == 0) s_sense = 0u;

    // Phase Z: zero degree counters + prep W1 split-bf16 + prep W2cat^T split-fp16
    for (int i = gt; i < N_NODES; i += GSTRIDE) g_idx[i] = 0;
    if (gt == 0) g_idx[N_NODES] = N_EDGES;
    for (int i = gt; i < 2 * 128 * 64; i += GSTRIDE) {
        int m = i >> 13;
        int rem = i & 8191;
        int n = rem >> 6;
        int c = rem & 63;
        const float* __restrict__ W = m ? Wr : Wl;
        float w0 = W[(2 * c)     * HID + n];
        float w1 = W[(2 * c + 1) * HID + n];
        g_Wth[i] = pack_hi(w0, w1);
        g_Wtl[i] = pack_lo(w0, w1);
    }
    for (int i = gt; i < 32 * 64; i += GSTRIDE) {
        int n = i >> 6, c = i & 63;
        float w0 = w2cat(Wl2, Wr2, 2 * c, n);
        float w1 = w2cat(Wl2, Wr2, 2 * c + 1, n);
        g_W2th[i] = pack_hi16(w0, w1);
        g_W2tl[i] = pack_lo16(w0, w1);
    }
    gbar(&s_sense);                                   // 1

    // Phase H: histogram of dst degrees
    for (int e = gt; e < N_EDGES; e += GSTRIDE)
        atomicAdd(&g_idx[__ldg(&ei[N_EDGES + e])], 1);
    gbar(&s_sense);                                   // 2

    // Phase S1: per-tile inclusive scan
    int d = 0;
    if (bid < SCAN_B) {
        int i = bid * 256 + tid;
        d = (i < N_NODES) ? g_idx[i] : 0;
        sh[tid] = d;
        __syncthreads();
        #pragma unroll
        for (int off = 1; off < 256; off <<= 1) {
            int v = (tid >= off) ? sh[tid - off] : 0;
            __syncthreads();
            sh[tid] += v;
            __syncthreads();
        }
        if (tid == 255) g_bsum[bid] = sh[255];
    }
    gbar(&s_sense);                                   // 3

    // Phase S2: block 0 scans tile sums
    int v0 = 0, v1 = 0;
    if (bid == 0) {
        v0 = (tid < SCAN_B) ? g_bsum[tid] : 0;
        v1 = (tid + 256 < SCAN_B) ? g_bsum[tid + 256] : 0;
        sh2[tid] = v0; sh2[tid + 256] = v1;
        __syncthreads();
        #pragma unroll
        for (int off = 1; off < 512; off <<= 1) {
            int a0 = (tid >= off) ? sh2[tid - off] : 0;
            int a1 = (tid + 256 >= off) ? sh2[tid + 256 - off] : 0;
            __syncthreads();
            sh2[tid] += a0;
            sh2[tid + 256] += a1;
            __syncthreads();
        }
        if (tid < SCAN_B) g_bsum[tid] = sh2[tid] - v0;
        if (tid + 256 < SCAN_B) g_bsum[tid + 256] = sh2[tid + 256] - v1;
    }
    gbar(&s_sense);                                   // 4

    // Phase S3: rowstart + cursor
    if (bid < SCAN_B) {
        int i = bid * 256 + tid;
        int r = g_bsum[bid] + sh[tid] - d;
        if (i < N_NODES) {
            g_idx[i]               = r;
            g_idx[N_NODES + 1 + i] = r;
        }
    }
    gbar(&s_sense);                                   // 5

    // Phase SC: scatter edges into CSR
    for (int e = gt; e < N_EDGES; e += GSTRIDE) {
        int dst = __ldg(&ei[N_EDGES + e]);
        int pos = atomicAdd(&g_idx[N_NODES + 1 + dst], 1);
        g_csr_src[pos] = __ldg(&ei[e]);
    }
    gbar(&s_sense);                                   // 6 (even -> sense returns to 0)
}

// ---------------- layer 0: agg(x,12) + FC(12->128) + relu -> packed bf16 h1 ----------------
// Gather: 2 edges per warp-iteration (lanes 0-11 edge e, lanes 12-23 edge e+1).
__global__ void layer0_kernel(const float* __restrict__ x,
                              const float* __restrict__ Wl,
                              const float* __restrict__ Wr,
                              const float* __restrict__ b) {
    __shared__ float sh[WPB][2 * IN_DIM];
    int w = threadIdx.x >> 5, lane = threadIdx.x & 31;
    int n = blockIdx.x * WPB + w;
    if (n >= N_NODES) return;

    int beg = g_idx[n], end = g_idx[n + 1];
    float acc = 0.f;
    if (lane < 24) {
        int sub = (lane >= IN_DIM) ? 1 : 0;
        int f   = (lane < IN_DIM) ? lane : lane - IN_DIM;
        for (int e = beg; e < end; e += 2) {
            int ee = e + sub;
            if (ee < end) {
                int src = g_csr_src[ee];
                acc += __ldg(&x[src * IN_DIM + f]);
            }
        }
    }
    // combine the two edge-halves: lane L (<12) += lane L+12
    float other = __shfl_sync(0xffffffffu, acc, (lane + IN_DIM) & 31);
    if (lane < IN_DIM) acc += other;

    int degn = end - beg;
    float cnt = (float)(degn > 0 ? degn : 1);
    if (lane < IN_DIM) {
        sh[w][lane]          = acc / cnt;
        sh[w][IN_DIM + lane] = __ldg(&x[n * IN_DIM + lane]);
    }
    __syncwarp();

    int j = 4 * lane;
    float4 a = *(const float4*)&b[j];
    #pragma unroll
    for (int k = 0; k < IN_DIM; k++) {
        float  m  = sh[w][k];
        float  xx = sh[w][IN_DIM + k];
        float4 wl = *(const float4*)&Wl[k * HID + j];
        float4 wr = *(const float4*)&Wr[k * HID + j];
        a.x += m * wl.x + xx * wr.x;
        a.y += m * wl.y + xx * wr.y;
        a.z += m * wl.z + xx * wr.z;
        a.w += m * wl.w + xx * wr.w;
    }
    a.x = fmaxf(a.x, 0.f); a.y = fmaxf(a.y, 0.f);
    a.z = fmaxf(a.z, 0.f); a.w = fmaxf(a.w, 0.f);

    size_t base = (size_t)n * 64 + 2 * lane;
    g_Ah[base]     = pack_hi(a.x, a.y);
    g_Ah[base + 1] = pack_hi(a.z, a.w);
    g_Al[base]     = pack_lo(a.x, a.y);
    g_Al[base + 1] = pack_lo(a.z, a.w);
}

// ---------------- tensor-core SGEMM: U(half)=h1@Wl1 (y=0), V(half)=h1@Wr1+b1 (y=1) ----------------
__global__ void sgemm_tc_kernel(const float* __restrict__ bias) {
    __shared__ unsigned As_h[64 * 20], As_l[64 * 20];
    __shared__ unsigned Bs_h[128 * 20], Bs_l[128 * 20];

    int tid = threadIdx.x, lane = tid & 31, wid = tid >> 5;
    int warp_m = wid >> 2, warp_n = wid & 3;
    int m_base = blockIdx.x * 64;
    int sel = blockIdx.y;
    const unsigned* __restrict__ Wt_h = g_Wth + sel * (128 * 64);
    const unsigned* __restrict__ Wt_l = g_Wtl + sel * (128 * 64);

    float acc[2][4][4];
    #pragma unroll
    for (int i = 0; i < 2; i++)
        #pragma unroll
        for (int jj = 0; jj < 4; jj++)
            acc[i][jj][0] = acc[i][jj][1] = acc[i][jj][2] = acc[i][jj][3] = 0.f;

    int ar = tid >> 2, ac4 = (tid & 3) * 4;
    int arow = m_base + ar; if (arow >= N_NODES) arow = N_NODES - 1;
    int bn = tid >> 1, bc8 = (tid & 1) * 8;

    for (int k0 = 0; k0 < 64; k0 += 16) {
        uint4 ah = *(const uint4*)&g_Ah[(size_t)arow * 64 + k0 + ac4];
        uint4 al = *(const uint4*)&g_Al[(size_t)arow * 64 + k0 + ac4];
        uint4 bh0 = *(const uint4*)&Wt_h[bn * 64 + k0 + bc8];
        uint4 bh1 = *(const uint4*)&Wt_h[bn * 64 + k0 + bc8 + 4];
        uint4 bl0 = *(const uint4*)&Wt_l[bn * 64 + k0 + bc8];
        uint4 bl1 = *(const uint4*)&Wt_l[bn * 64 + k0 + bc8 + 4];
        __syncthreads();
        *(uint4*)&As_h[ar * 20 + ac4] = ah;
        *(uint4*)&As_l[ar * 20 + ac4] = al;
        *(uint4*)&Bs_h[bn * 20 + bc8]     = bh0;
        *(uint4*)&Bs_h[bn * 20 + bc8 + 4] = bh1;
        *(uint4*)&Bs_l[bn * 20 + bc8]     = bl0;
        *(uint4*)&Bs_l[bn * 20 + bc8 + 4] = bl1;
        __syncthreads();

        #pragma unroll
        for (int ks = 0; ks < 2; ks++) {
            int cb = ks * 8 + (lane & 3);
            unsigned a_h[2][4], a_l[2][4];
            #pragma unroll
            for (int tm = 0; tm < 2; tm++) {
                int r0 = (warp_m * 32 + tm * 16 + (lane >> 2)) * 20 + cb;
                a_h[tm][0] = As_h[r0];            a_h[tm][1] = As_h[r0 + 8 * 20];
                a_h[tm][2] = As_h[r0 + 4];        a_h[tm][3] = As_h[r0 + 8 * 20 + 4];
                a_l[tm][0] = As_l[r0];            a_l[tm][1] = As_l[r0 + 8 * 20];
                a_l[tm][2] = As_l[r0 + 4];        a_l[tm][3] = As_l[r0 + 8 * 20 + 4];
            }
            unsigned b_h[4][2], b_l[4][2];
            #pragma unroll
            for (int tn = 0; tn < 4; tn++) {
                int q = (warp_n * 32 + tn * 8 + (lane >> 2)) * 20 + cb;
                b_h[tn][0] = Bs_h[q]; b_h[tn][1] = Bs_h[q + 4];
                b_l[tn][0] = Bs_l[q]; b_l[tn][1] = Bs_l[q + 4];
            }
            #pragma unroll
            for (int tm = 0; tm < 2; tm++)
                #pragma unroll
                for (int tn = 0; tn < 4; tn++) {
                    MMA_BF16(acc[tm][tn], a_h[tm], b_h[tn]);
                    MMA_BF16(acc[tm][tn], a_h[tm], b_l[tn]);
                    MMA_BF16(acc[tm][tn], a_l[tm], b_h[tn]);
                }
        }
    }

    unsigned* __restrict__ C16 = sel ? g_V16 : g_U16;
    #pragma unroll
    for (int tn = 0; tn < 4; tn++) {
        int col = warp_n * 32 + tn * 8 + 2 * (lane & 3);
        float bx = 0.f, by = 0.f;
        if (sel) { bx = __ldg(&bias[col]); by = __ldg(&bias[col + 1]); }
        #pragma unroll
        for (int tm = 0; tm < 2; tm++) {
            int row0 = m_base + warp_m * 32 + tm * 16 + (lane >> 2);
            if (row0 < N_NODES) {
                __half2 h = __floats2half2_rn(acc[tm][tn][0] + bx, acc[tm][tn][1] + by);
                C16[(size_t)row0 * 64 + col / 2] = *(unsigned*)&h;
            }
            int row1 = row0 + 8;
            if (row1 < N_NODES) {
                __half2 h = __floats2half2_rn(acc[tm][tn][2] + bx, acc[tm][tn][3] + by);
                C16[(size_t)row1 * 64 + col / 2] = *(unsigned*)&h;
            }
        }
    }
}

// ---------------- agg2: h2 = relu(mean(U16[nbrs]) + V16[n]) -> packed fp16 g_H2 ----------------
// Pure gather; 2 edges per warp-iteration; no shared memory. (R12 version, proven 67.9us.)
__global__ void agg2_kernel() {
    int w = threadIdx.x >> 5, lane = threadIdx.x & 31;
    int n = blockIdx.x * WPB_F + w;
    if (n >= N_NODES) return;

    int beg = g_idx[n], end = g_idx[n + 1];
    int half = lane >> 4;
    int fl   = lane & 15;
    float acc[8];
    #pragma unroll
    for (int i = 0; i < 8; i++) acc[i] = 0.f;

    #pragma unroll 2
    for (int e = beg; e < end; e += 2) {
        int ee = e + half;
        if (ee < end) {
            int src = g_csr_src[ee];
            uint4 u = *(const uint4*)&g_U16[(size_t)src * 64 + 4 * fl];
            float2 f0 = __half22float2(*(const __half2*)&u.x);
            float2 f1 = __half22float2(*(const __half2*)&u.y);
            float2 f2 = __half22float2(*(const __half2*)&u.z);
            float2 f3 = __half22float2(*(const __half2*)&u.w);
            acc[0] += f0.x; acc[1] += f0.y;
            acc[2] += f1.x; acc[3] += f1.y;
            acc[4] += f2.x; acc[5] += f2.y;
            acc[6] += f3.x; acc[7] += f3.y;
        }
    }
    #pragma unroll
    for (int i = 0; i < 8; i++)
        acc[i] += __shfl_xor_sync(0xffffffffu, acc[i], 16);

    int degn = end - beg;
    float inv = 1.f / (float)(degn > 0 ? degn : 1);
    if (half == 0) {
        uint4 vv = *(const uint4*)&g_V16[(size_t)n * 64 + 4 * fl];
        float2 v0 = __half22float2(*(const __half2*)&vv.x);
        float2 v1 = __half22float2(*(const __half2*)&vv.y);
        float2 v2 = __half22float2(*(const __half2*)&vv.z);
        float2 v3 = __half22float2(*(const __half2*)&vv.w);
        uint4 o;
        o.x = pack_hi16(fmaxf(acc[0] * inv + v0.x, 0.f), fmaxf(acc[1] * inv + v0.y, 0.f));
        o.y = pack_hi16(fmaxf(acc[2] * inv + v1.x, 0.f), fmaxf(acc[3] * inv + v1.y, 0.f));
        o.z = pack_hi16(fmaxf(acc[4] * inv + v2.x, 0.f), fmaxf(acc[5] * inv + v2.y, 0.f));
        o.w = pack_hi16(fmaxf(acc[6] * inv + v3.x, 0.f), fmaxf(acc[7] * inv + v3.y, 0.f));
        *(uint4*)&g_H2[(size_t)n * 64 + 4 * fl] = o;
    }
}

// ---------------- gemm2_tc: [u2|v2|pads] = H2 @ W2cat  (M=64/block, N=32, K=128) ----------------
__global__ void __launch_bounds__(128)
gemm2_tc_kernel(const float* __restrict__ b2) {
    __shared__ unsigned As[64 * 68];       // h2 tile, stride 68 half2
    __shared__ unsigned Bs_h[32 * 66];     // W2cat^T hi, stride 66
    __shared__ unsigned Bs_l[32 * 66];

    int tid = threadIdx.x, lane = tid & 31, wid = tid >> 5;   // 4 warps
    int m_base = blockIdx.x * 64;

    // load A tile: 64 rows x 64 half2 (8 uint4 per thread)
    {
        int row = tid >> 1;
        int g_row = m_base + row; if (g_row >= N_NODES) g_row = N_NODES - 1;
        int cbase = (tid & 1) * 8;
        #pragma unroll
        for (int i = 0; i < 8; i++) {
            uint4 v = *(const uint4*)&g_H2[(size_t)g_row * 64 + (cbase + i) * 4];
            *(uint4*)&As[row * 68 + (cbase + i) * 4] = v;
        }
    }
    // load B tiles
    for (int i = tid; i < 32 * 64; i += 128) {
        int r = i >> 6, c = i & 63;
        Bs_h[r * 66 + c] = g_W2th[i];
        Bs_l[r * 66 + c] = g_W2tl[i];
    }
    __syncthreads();

    float acc[4][4];
    #pragma unroll
    for (int tn = 0; tn < 4; tn++)
        acc[tn][0] = acc[tn][1] = acc[tn][2] = acc[tn][3] = 0.f;

    #pragma unroll
    for (int ks = 0; ks < 8; ks++) {
        int cb = ks * 8 + (lane & 3);
        unsigned a[4];
        int r0 = (16 * wid + (lane >> 2)) * 68 + cb;
        a[0] = As[r0];           a[1] = As[r0 + 8 * 68];
        a[2] = As[r0 + 4];       a[3] = As[r0 + 8 * 68 + 4];
        #pragma unroll
        for (int tn = 0; tn < 4; tn++) {
            int q = (tn * 8 + (lane >> 2)) * 66 + cb;
            unsigned bh[2] = { Bs_h[q], Bs_h[q + 4] };
            unsigned bl[2] = { Bs_l[q], Bs_l[q + 4] };
            MMA_F16(acc[tn], a, bh);
            MMA_F16(acc[tn], a, bl);
        }
    }

    #pragma unroll
    for (int tn = 0; tn < 4; tn++) {
        int n0 = tn * 8 + 2 * (lane & 3);
        #pragma unroll
        for (int half = 0; half < 2; half++) {
            int node = m_base + 16 * wid + (lane >> 2) + 8 * half;
            if (node < N_NODES) {
                float va = acc[tn][2 * half], vb = acc[tn][2 * half + 1];
                #pragma unroll
                for (int p = 0; p < 2; p++) {
                    int nn = n0 + p;
                    float v = p ? vb : va;
                    if (nn < OUT_DIM) {
                        g_u2[(size_t)node * 16 + nn] = v;
                    } else if (nn < 2 * OUT_DIM) {
                        g_v2[(size_t)node * 16 + (nn - OUT_DIM)] = v + __ldg(&b2[nn - OUT_DIM]);
                    } else if (nn < 29) {
                        g_u2[(size_t)node * 16 + (nn - OUT_DIM)] = 0.f;  // u2 pads 13..15
                    }
                }
            }
        }
    }
}

// ---------------- final: out = hiermax(sigmoid(mean(u2[nbrs]) + v2[n])) ----------------
// Gather: 4 edges per warp-iteration; 8 lanes per edge, float2 per lane.
__global__ void aggF_kernel(const int* __restrict__ R, float* __restrict__ out) {
    __shared__ float s[WPB_F][16];
    int w = threadIdx.x >> 5, lane = threadIdx.x & 31;
    int n = blockIdx.x * WPB_F + w;
    if (n >= N_NODES) return;

    int beg = g_idx[n], end = g_idx[n + 1];
    int grp = lane >> 3;      // edge offset 0..3
    int fp  = lane & 7;       // feature pair (floats 2fp, 2fp+1)
    float2 acc = make_float2(0.f, 0.f);
    #pragma unroll 2
    for (int e = beg; e < end; e += 4) {
        int ee = e + grp;
        if (ee < end) {
            int src = g_csr_src[ee];
            float2 v = *(const float2*)&g_u2[(size_t)src * 16 + 2 * fp];
            acc.x += v.x; acc.y += v.y;
        }
    }
    acc.x += __shfl_xor_sync(0xffffffffu, acc.x, 8);
    acc.y += __shfl_xor_sync(0xffffffffu, acc.y, 8);
    acc.x += __shfl_xor_sync(0xffffffffu, acc.x, 16);
    acc.y += __shfl_xor_sync(0xffffffffu, acc.y, 16);

    int degn = end - beg;
    float inv = 1.f / (float)(degn > 0 ? degn : 1);
    if (lane < 8) {                              // lane == fp here
        int f0 = 2 * lane, f1 = f0 + 1;
        if (f0 < OUT_DIM) {
            float z = acc.x * inv + g_v2[(size_t)n * 16 + f0];
            s[w][f0] = 1.f / (1.f + expf(-z));
        }
        if (f1 < OUT_DIM) {
            float z = acc.y * inv + g_v2[(size_t)n * 16 + f1];
            s[w][f1] = 1.f / (1.f + expf(-z));
        }
    }
    __syncwarp();
    if (lane < OUT_DIM) {
        float mx = 0.f;
        #pragma unroll
        for (int jj = 0; jj < OUT_DIM; jj++) {
            if (__ldg(&R[lane * OUT_DIM + jj])) mx = fmaxf(mx, s[w][jj]);
        }
        out[(size_t)n * OUT_DIM + lane] = mx;
    }
}

// ---------------- launch ----------------
extern "C" void kernel_launch(void* const* d_in, const int* in_sizes, int n_in,
                              void* d_out, int out_size) {
    const float* x   = (const float*)d_in[0];
    const float* Wl0 = (const float*)d_in[1];
    const float* Wr0 = (const float*)d_in[2];
    const float* b0  = (const float*)d_in[3];
    const float* Wl1 = (const float*)d_in[4];
    const float* Wr1 = (const float*)d_in[5];
    const float* b1  = (const float*)d_in[6];
    const float* Wl2 = (const float*)d_in[7];
    const float* Wr2 = (const float*)d_in[8];
    const float* b2  = (const float*)d_in[9];
    const int*   ei  = (const int*)d_in[10];
    const int*   R   = (const int*)d_in[11];
    float* out = (float*)d_out;
    (void)in_sizes; (void)n_in; (void)out_size;

    csr_coop_kernel<<<GRID_C, 256>>>(ei, Wl1, Wr1, Wl2, Wr2);      // launch 1

    int nb = (N_NODES + WPB - 1) / WPB;
    layer0_kernel<<<nb, WPB * 32>>>(x, Wl0, Wr0, b0);              // launch 2

    dim3 gg((N_NODES + 63) / 64, 2);
    sgemm_tc_kernel<<<gg, 256>>>(b1);                              // launch 3

    int nbf = (N_NODES + WPB_F - 1) / WPB_F;
    agg2_kernel<<<nbf, WPB_F * 32>>>();                            // launch 4 <- profiled

    gemm2_tc_kernel<<<(N_NODES + 63) / 64, 128>>>(b2);             // launch 5
    aggF_kernel<<<nbf, WPB_F * 32>>>(R, out);                      // launch 6
}

// round 15
// speedup vs baseline: 1.1177x; 1.0237x over previous
#include <cuda_runtime.h>
#include <cuda_bf16.h>
#include <cuda_fp16.h>

#define N_NODES 100000
#define N_EDGES 1600000
#define IN_DIM  12
#define HID     128
#define OUT_DIM 13
#define WPB     8      // warps per block (layer0)
#define WPB_F   16     // warps per block (agg kernels)
#define SCAN_B  391    // ceil(N_NODES/256)
#define GRID_C  512    // persistent CSR kernel grid

// ---------------- scratch (static device globals; no allocation) ----------------
__device__ int      g_idx[2 * N_NODES + 1];        // rowstart | cursor
__device__ int      g_bsum[512];                   // scan block sums
__device__ int      g_csr_src[N_EDGES];
__device__ unsigned g_U16[(size_t)N_NODES * 64];   // h1 @ Wl1, packed half2
__device__ unsigned g_V16[(size_t)N_NODES * 64];   // h1 @ Wr1 + b1, packed half2
__device__ unsigned g_H2[(size_t)N_NODES * 64];    // h2, packed half2
__device__ unsigned g_Ah[(size_t)N_NODES * 64];    // h1 packed bf16x2 (hi)
__device__ unsigned g_Al[(size_t)N_NODES * 64];    // h1 packed bf16x2 (lo)
__device__ unsigned g_Wth[2 * 128 * 64];           // W1^T packed bf16x2 hi: [m][n][kpair]
__device__ unsigned g_Wtl[2 * 128 * 64];           // lo
__device__ unsigned g_W2th[32 * 64];               // W2cat^T packed half2 hi: [n][kpair]
__device__ unsigned g_W2tl[32 * 64];               // lo
__device__ float    g_u2[(size_t)N_NODES * 16];    // h2 @ Wl2 (13, pad 16 — pads zeroed)
__device__ float    g_v2[(size_t)N_NODES * 16];    // h2 @ Wr2 + b2
__device__ unsigned g_bar_count;
__device__ unsigned g_bar_sense;

// ---------------- helpers ----------------
__device__ __forceinline__ unsigned pack_hi(float x, float y) {
    __nv_bfloat16 bx = __float2bfloat16(x);
    __nv_bfloat16 by = __float2bfloat16(y);
    return ((unsigned)__bfloat16_as_ushort(by) << 16) | __bfloat16_as_ushort(bx);
}
__device__ __forceinline__ unsigned pack_lo(float x, float y) {
    float rx = x - __bfloat162float(__float2bfloat16(x));
    float ry = y - __bfloat162float(__float2bfloat16(y));
    __nv_bfloat16 bx = __float2bfloat16(rx);
    __nv_bfloat16 by = __float2bfloat16(ry);
    return ((unsigned)__bfloat16_as_ushort(by) << 16) | __bfloat16_as_ushort(bx);
}
__device__ __forceinline__ unsigned pack_hi16(float x, float y) {
    __half2 h = __floats2half2_rn(x, y);
    return *(unsigned*)&h;
}
__device__ __forceinline__ unsigned pack_lo16(float x, float y) {
    float rx = x - __half2float(__float2half_rn(x));
    float ry = y - __half2float(__float2half_rn(y));
    __half2 h = __floats2half2_rn(rx, ry);
    return *(unsigned*)&h;
}

#define MMA_BF16(d, a, b)                                                        \
    asm volatile(                                                                \
        "mma.sync.aligned.m16n8k16.row.col.f32.bf16.bf16.f32 "                   \
        "{%0,%1,%2,%3}, {%4,%5,%6,%7}, {%8,%9}, {%0,%1,%2,%3};\n"                \
        : "+f"((d)[0]), "+f"((d)[1]), "+f"((d)[2]), "+f"((d)[3])                 \
        : "r"((a)[0]), "r"((a)[1]), "r"((a)[2]), "r"((a)[3]),                    \
          "r"((b)[0]), "r"((b)[1]))

#define MMA_F16(d, a, b)                                                         \
    asm volatile(                                                                \
        "mma.sync.aligned.m16n8k16.row.col.f32.f16.f16.f32 "                     \
        "{%0,%1,%2,%3}, {%4,%5,%6,%7}, {%8,%9}, {%0,%1,%2,%3};\n"                \
        : "+f"((d)[0]), "+f"((d)[1]), "+f"((d)[2]), "+f"((d)[3])                 \
        : "r"((a)[0]), "r"((a)[1]), "r"((a)[2]), "r"((a)[3]),                    \
          "r"((b)[0]), "r"((b)[1]))

// ---------------- prep: W1 split-bf16 + W2cat split-fp16 ----------------
__device__ __forceinline__ float w2cat(const float* Wl2, const float* Wr2, int k, int n) {
    if (n < OUT_DIM) return Wl2[k * OUT_DIM + n];
    if (n < 2 * OUT_DIM) return Wr2[k * OUT_DIM + (n - OUT_DIM)];
    return 0.f;
}

__global__ void prepw_kernel(const float* __restrict__ Wl,
                             const float* __restrict__ Wr,
                             const float* __restrict__ Wl2,
                             const float* __restrict__ Wr2) {
    int i = blockIdx.x * blockDim.x + threadIdx.x;
    if (i < 2 * 128 * 64) {
        int m = i >> 13;
        int rem = i & 8191;
        int n = rem >> 6;
        int c = rem & 63;
        const float* __restrict__ W = m ? Wr : Wl;
        float w0 = W[(2 * c)     * HID + n];
        float w1 = W[(2 * c + 1) * HID + n];
        g_Wth[i] = pack_hi(w0, w1);
        g_Wtl[i] = pack_lo(w0, w1);
    } else if (i < 2 * 128 * 64 + 32 * 64) {
        int j = i - 2 * 128 * 64;
        int n = j >> 6, c = j & 63;
        float w0 = w2cat(Wl2, Wr2, 2 * c, n);
        float w1 = w2cat(Wl2, Wr2, 2 * c + 1, n);
        g_W2th[j] = pack_hi16(w0, w1);
        g_W2tl[j] = pack_lo16(w0, w1);
    }
}

// ---------------- persistent CSR build ----------------
__device__ __forceinline__ void gbar(unsigned* s_sense) {
    __syncthreads();
    if (threadIdx.x == 0) {
        unsigned s = *s_sense ^ 1u;
        __threadfence();
        if (atomicAdd(&g_bar_count, 1u) == GRID_C - 1u) {
            g_bar_count = 0u;
            __threadfence();
            atomicExch(&g_bar_sense, s);
        } else {
            while (atomicAdd(&g_bar_sense, 0u) != s) __nanosleep(64);
        }
        __threadfence();
        *s_sense = s;
    }
    __syncthreads();
}

__global__ void __launch_bounds__(256, 8)
csr_coop_kernel(const int* __restrict__ ei) {
    __shared__ int sh[256];
    __shared__ int sh2[512];
    __shared__ unsigned s_sense;
    int tid = threadIdx.x, bid = blockIdx.x;
    int gt = bid * 256 + tid;
    const int GSTRIDE = GRID_C * 256;
    if (tid == 0) s_sense = 0u;

    // Phase Z: zero degree counters
    for (int i = gt; i < N_NODES; i += GSTRIDE) g_idx[i] = 0;
    if (gt == 0) g_idx[N_NODES] = N_EDGES;
    gbar(&s_sense);                                   // 1

    // Phase H: histogram of dst degrees
    for (int e = gt; e < N_EDGES; e += GSTRIDE)
        atomicAdd(&g_idx[__ldg(&ei[N_EDGES + e])], 1);
    gbar(&s_sense);                                   // 2

    // Phase S1: per-tile inclusive scan
    int d = 0;
    if (bid < SCAN_B) {
        int i = bid * 256 + tid;
        d = (i < N_NODES) ? g_idx[i] : 0;
        sh[tid] = d;
        __syncthreads();
        #pragma unroll
        for (int off = 1; off < 256; off <<= 1) {
            int v = (tid >= off) ? sh[tid - off] : 0;
            __syncthreads();
            sh[tid] += v;
            __syncthreads();
        }
        if (tid == 255) g_bsum[bid] = sh[255];
    }
    gbar(&s_sense);                                   // 3

    // Phase S2: block 0 scans tile sums
    int v0 = 0, v1 = 0;
    if (bid == 0) {
        v0 = (tid < SCAN_B) ? g_bsum[tid] : 0;
        v1 = (tid + 256 < SCAN_B) ? g_bsum[tid + 256] : 0;
        sh2[tid] = v0; sh2[tid + 256] = v1;
        __syncthreads();
        #pragma unroll
        for (int off = 1; off < 512; off <<= 1) {
            int a0 = (tid >= off) ? sh2[tid - off] : 0;
            int a1 = (tid + 256 >= off) ? sh2[tid + 256 - off] : 0;
            __syncthreads();
            sh2[tid] += a0;
            sh2[tid + 256] += a1;
            __syncthreads();
        }
        if (tid < SCAN_B) g_bsum[tid] = sh2[tid] - v0;
        if (tid + 256 < SCAN_B) g_bsum[tid + 256] = sh2[tid + 256] - v1;
    }
    gbar(&s_sense);                                   // 4

    // Phase S3: rowstart + cursor
    if (bid < SCAN_B) {
        int i = bid * 256 + tid;
        int r = g_bsum[bid] + sh[tid] - d;
        if (i < N_NODES) {
            g_idx[i]               = r;
            g_idx[N_NODES + 1 + i] = r;
        }
    }
    gbar(&s_sense);                                   // 5

    // Phase SC: scatter edges into CSR
    for (int e = gt; e < N_EDGES; e += GSTRIDE) {
        int dst = __ldg(&ei[N_EDGES + e]);
        int pos = atomicAdd(&g_idx[N_NODES + 1 + dst], 1);
        g_csr_src[pos] = __ldg(&ei[e]);
    }
    gbar(&s_sense);                                   // 6 (even -> sense returns to 0)
}

// ---------------- layer 0: agg(x,12) + FC(12->128) + relu -> packed bf16 h1 ----------------
// Gather: 2 edges per warp-iteration (lanes 0-11 edge e, lanes 12-23 edge e+1).
__global__ void layer0_kernel(const float* __restrict__ x,
                              const float* __restrict__ Wl,
                              const float* __restrict__ Wr,
                              const float* __restrict__ b) {
    __shared__ float sh[WPB][2 * IN_DIM];
    int w = threadIdx.x >> 5, lane = threadIdx.x & 31;
    int n = blockIdx.x * WPB + w;
    if (n >= N_NODES) return;

    int beg = g_idx[n], end = g_idx[n + 1];
    float acc = 0.f;
    if (lane < 24) {
        int sub = (lane >= IN_DIM) ? 1 : 0;
        int f   = (lane < IN_DIM) ? lane : lane - IN_DIM;
        for (int e = beg; e < end; e += 2) {
            int ee = e + sub;
            if (ee < end) {
                int src = g_csr_src[ee];
                acc += __ldg(&x[src * IN_DIM + f]);
            }
        }
    }
    float other = __shfl_sync(0xffffffffu, acc, (lane + IN_DIM) & 31);
    if (lane < IN_DIM) acc += other;

    int degn = end - beg;
    float cnt = (float)(degn > 0 ? degn : 1);
    if (lane < IN_DIM) {
        sh[w][lane]          = acc / cnt;
        sh[w][IN_DIM + lane] = __ldg(&x[n * IN_DIM + lane]);
    }
    __syncwarp();

    int j = 4 * lane;
    float4 a = *(const float4*)&b[j];
    #pragma unroll
    for (int k = 0; k < IN_DIM; k++) {
        float  m  = sh[w][k];
        float  xx = sh[w][IN_DIM + k];
        float4 wl = *(const float4*)&Wl[k * HID + j];
        float4 wr = *(const float4*)&Wr[k * HID + j];
        a.x += m * wl.x + xx * wr.x;
        a.y += m * wl.y + xx * wr.y;
        a.z += m * wl.z + xx * wr.z;
        a.w += m * wl.w + xx * wr.w;
    }
    a.x = fmaxf(a.x, 0.f); a.y = fmaxf(a.y, 0.f);
    a.z = fmaxf(a.z, 0.f); a.w = fmaxf(a.w, 0.f);

    size_t base = (size_t)n * 64 + 2 * lane;
    g_Ah[base]     = pack_hi(a.x, a.y);
    g_Ah[base + 1] = pack_hi(a.z, a.w);
    g_Al[base]     = pack_lo(a.x, a.y);
    g_Al[base + 1] = pack_lo(a.z, a.w);
}

// ---------------- tensor-core SGEMM: U(half)=h1@Wl1 (y=0), V(half)=h1@Wr1+b1 (y=1) ----------------
__global__ void sgemm_tc_kernel(const float* __restrict__ bias) {
    __shared__ unsigned As_h[64 * 20], As_l[64 * 20];
    __shared__ unsigned Bs_h[128 * 20], Bs_l[128 * 20];

    int tid = threadIdx.x, lane = tid & 31, wid = tid >> 5;
    int warp_m = wid >> 2, warp_n = wid & 3;
    int m_base = blockIdx.x * 64;
    int sel = blockIdx.y;
    const unsigned* __restrict__ Wt_h = g_Wth + sel * (128 * 64);
    const unsigned* __restrict__ Wt_l = g_Wtl + sel * (128 * 64);

    float acc[2][4][4];
    #pragma unroll
    for (int i = 0; i < 2; i++)
        #pragma unroll
        for (int jj = 0; jj < 4; jj++)
            acc[i][jj][0] = acc[i][jj][1] = acc[i][jj][2] = acc[i][jj][3] = 0.f;

    int ar = tid >> 2, ac4 = (tid & 3) * 4;
    int arow = m_base + ar; if (arow >= N_NODES) arow = N_NODES - 1;
    int bn = tid >> 1, bc8 = (tid & 1) * 8;

    for (int k0 = 0; k0 < 64; k0 += 16) {
        uint4 ah = *(const uint4*)&g_Ah[(size_t)arow * 64 + k0 + ac4];
        uint4 al = *(const uint4*)&g_Al[(size_t)arow * 64 + k0 + ac4];
        uint4 bh0 = *(const uint4*)&Wt_h[bn * 64 + k0 + bc8];
        uint4 bh1 = *(const uint4*)&Wt_h[bn * 64 + k0 + bc8 + 4];
        uint4 bl0 = *(const uint4*)&Wt_l[bn * 64 + k0 + bc8];
        uint4 bl1 = *(const uint4*)&Wt_l[bn * 64 + k0 + bc8 + 4];
        __syncthreads();
        *(uint4*)&As_h[ar * 20 + ac4] = ah;
        *(uint4*)&As_l[ar * 20 + ac4] = al;
        *(uint4*)&Bs_h[bn * 20 + bc8]     = bh0;
        *(uint4*)&Bs_h[bn * 20 + bc8 + 4] = bh1;
        *(uint4*)&Bs_l[bn * 20 + bc8]     = bl0;
        *(uint4*)&Bs_l[bn * 20 + bc8 + 4] = bl1;
        __syncthreads();

        #pragma unroll
        for (int ks = 0; ks < 2; ks++) {
            int cb = ks * 8 + (lane & 3);
            unsigned a_h[2][4], a_l[2][4];
            #pragma unroll
            for (int tm = 0; tm < 2; tm++) {
                int r0 = (warp_m * 32 + tm * 16 + (lane >> 2)) * 20 + cb;
                a_h[tm][0] = As_h[r0];            a_h[tm][1] = As_h[r0 + 8 * 20];
                a_h[tm][2] = As_h[r0 + 4];        a_h[tm][3] = As_h[r0 + 8 * 20 + 4];
                a_l[tm][0] = As_l[r0];            a_l[tm][1] = As_l[r0 + 8 * 20];
                a_l[tm][2] = As_l[r0 + 4];        a_l[tm][3] = As_l[r0 + 8 * 20 + 4];
            }
            unsigned b_h[4][2], b_l[4][2];
            #pragma unroll
            for (int tn = 0; tn < 4; tn++) {
                int q = (warp_n * 32 + tn * 8 + (lane >> 2)) * 20 + cb;
                b_h[tn][0] = Bs_h[q]; b_h[tn][1] = Bs_h[q + 4];
                b_l[tn][0] = Bs_l[q]; b_l[tn][1] = Bs_l[q + 4];
            }
            #pragma unroll
            for (int tm = 0; tm < 2; tm++)
                #pragma unroll
                for (int tn = 0; tn < 4; tn++) {
                    MMA_BF16(acc[tm][tn], a_h[tm], b_h[tn]);
                    MMA_BF16(acc[tm][tn], a_h[tm], b_l[tn]);
                    MMA_BF16(acc[tm][tn], a_l[tm], b_h[tn]);
                }
        }
    }

    unsigned* __restrict__ C16 = sel ? g_V16 : g_U16;
    #pragma unroll
    for (int tn = 0; tn < 4; tn++) {
        int col = warp_n * 32 + tn * 8 + 2 * (lane & 3);
        float bx = 0.f, by = 0.f;
        if (sel) { bx = __ldg(&bias[col]); by = __ldg(&bias[col + 1]); }
        #pragma unroll
        for (int tm = 0; tm < 2; tm++) {
            int row0 = m_base + warp_m * 32 + tm * 16 + (lane >> 2);
            if (row0 < N_NODES) {
                __half2 h = __floats2half2_rn(acc[tm][tn][0] + bx, acc[tm][tn][1] + by);
                C16[(size_t)row0 * 64 + col / 2] = *(unsigned*)&h;
            }
            int row1 = row0 + 8;
            if (row1 < N_NODES) {
                __half2 h = __floats2half2_rn(acc[tm][tn][2] + bx, acc[tm][tn][3] + by);
                C16[(size_t)row1 * 64 + col / 2] = *(unsigned*)&h;
            }
        }
    }
}

// ---------------- agg2: h2 = relu(mean(U16[nbrs]) + V16[n]) -> packed fp16 g_H2 ----------------
// Pure gather; 4 edges per warp-iteration via manual 2x unroll per lane (MLP=2/lane).
__global__ void agg2_kernel() {
    int w = threadIdx.x >> 5, lane = threadIdx.x & 31;
    int n = blockIdx.x * WPB_F + w;
    if (n >= N_NODES) return;

    int beg = g_idx[n], end = g_idx[n + 1];
    int half = lane >> 4;
    int fl   = lane & 15;
    float acc[8];
    #pragma unroll
    for (int i = 0; i < 8; i++) acc[i] = 0.f;

    int e = beg + half;
    while (e + 2 < end) {                        // two edges for this lane: e, e+2
        int s0 = g_csr_src[e];
        int s1 = g_csr_src[e + 2];
        uint4 u0 = *(const uint4*)&g_U16[(size_t)s0 * 64 + 4 * fl];
        uint4 u1 = *(const uint4*)&g_U16[(size_t)s1 * 64 + 4 * fl];
        float2 f;
        f = __half22float2(*(const __half2*)&u0.x); acc[0] += f.x; acc[1] += f.y;
        f = __half22float2(*(const __half2*)&u0.y); acc[2] += f.x; acc[3] += f.y;
        f = __half22float2(*(const __half2*)&u0.z); acc[4] += f.x; acc[5] += f.y;
        f = __half22float2(*(const __half2*)&u0.w); acc[6] += f.x; acc[7] += f.y;
        f = __half22float2(*(const __half2*)&u1.x); acc[0] += f.x; acc[1] += f.y;
        f = __half22float2(*(const __half2*)&u1.y); acc[2] += f.x; acc[3] += f.y;
        f = __half22float2(*(const __half2*)&u1.z); acc[4] += f.x; acc[5] += f.y;
        f = __half22float2(*(const __half2*)&u1.w); acc[6] += f.x; acc[7] += f.y;
        e += 4;
    }
    if (e < end) {
        int s0 = g_csr_src[e];
        uint4 u0 = *(const uint4*)&g_U16[(size_t)s0 * 64 + 4 * fl];
        float2 f;
        f = __half22float2(*(const __half2*)&u0.x); acc[0] += f.x; acc[1] += f.y;
        f = __half22float2(*(const __half2*)&u0.y); acc[2] += f.x; acc[3] += f.y;
        f = __half22float2(*(const __half2*)&u0.z); acc[4] += f.x; acc[5] += f.y;
        f = __half22float2(*(const __half2*)&u0.w); acc[6] += f.x; acc[7] += f.y;
    }
    #pragma unroll
    for (int i = 0; i < 8; i++)
        acc[i] += __shfl_xor_sync(0xffffffffu, acc[i], 16);

    int degn = end - beg;
    float inv = 1.f / (float)(degn > 0 ? degn : 1);
    if (half == 0) {
        uint4 vv = *(const uint4*)&g_V16[(size_t)n * 64 + 4 * fl];
        float2 v0 = __half22float2(*(const __half2*)&vv.x);
        float2 v1 = __half22float2(*(const __half2*)&vv.y);
        float2 v2 = __half22float2(*(const __half2*)&vv.z);
        float2 v3 = __half22float2(*(const __half2*)&vv.w);
        uint4 o;
        o.x = pack_hi16(fmaxf(acc[0] * inv + v0.x, 0.f), fmaxf(acc[1] * inv + v0.y, 0.f));
        o.y = pack_hi16(fmaxf(acc[2] * inv + v1.x, 0.f), fmaxf(acc[3] * inv + v1.y, 0.f));
        o.z = pack_hi16(fmaxf(acc[4] * inv + v2.x, 0.f), fmaxf(acc[5] * inv + v2.y, 0.f));
        o.w = pack_hi16(fmaxf(acc[6] * inv + v3.x, 0.f), fmaxf(acc[7] * inv + v3.y, 0.f));
        *(uint4*)&g_H2[(size_t)n * 64 + 4 * fl] = o;
    }
}

// ---------------- gemm2_tc: [u2|v2|pads] = H2 @ W2cat  (M=64/block, N=32, K=128) ----------------
__global__ void __launch_bounds__(128)
gemm2_tc_kernel(const float* __restrict__ b2) {
    __shared__ unsigned As[64 * 68];       // h2 tile, stride 68 half2
    __shared__ unsigned Bs_h[32 * 66];     // W2cat^T hi, stride 66
    __shared__ unsigned Bs_l[32 * 66];

    int tid = threadIdx.x, lane = tid & 31, wid = tid >> 5;   // 4 warps
    int m_base = blockIdx.x * 64;

    {
        int row = tid >> 1;
        int g_row = m_base + row; if (g_row >= N_NODES) g_row = N_NODES - 1;
        int cbase = (tid & 1) * 8;
        #pragma unroll
        for (int i = 0; i < 8; i++) {
            uint4 v = *(const uint4*)&g_H2[(size_t)g_row * 64 + (cbase + i) * 4];
            *(uint4*)&As[row * 68 + (cbase + i) * 4] = v;
        }
    }
    for (int i = tid; i < 32 * 64; i += 128) {
        int r = i >> 6, c = i & 63;
        Bs_h[r * 66 + c] = g_W2th[i];
        Bs_l[r * 66 + c] = g_W2tl[i];
    }
    __syncthreads();

    float acc[4][4];
    #pragma unroll
    for (int tn = 0; tn < 4; tn++)
        acc[tn][0] = acc[tn][1] = acc[tn][2] = acc[tn][3] = 0.f;

    #pragma unroll
    for (int ks = 0; ks < 8; ks++) {
        int cb = ks * 8 + (lane & 3);
        unsigned a[4];
        int r0 = (16 * wid + (lane >> 2)) * 68 + cb;
        a[0] = As[r0];           a[1] = As[r0 + 8 * 68];
        a[2] = As[r0 + 4];       a[3] = As[r0 + 8 * 68 + 4];
        #pragma unroll
        for (int tn = 0; tn < 4; tn++) {
            int q = (tn * 8 + (lane >> 2)) * 66 + cb;
            unsigned bh[2] = { Bs_h[q], Bs_h[q + 4] };
            unsigned bl[2] = { Bs_l[q], Bs_l[q + 4] };
            MMA_F16(acc[tn], a, bh);
            MMA_F16(acc[tn], a, bl);
        }
    }

    #pragma unroll
    for (int tn = 0; tn < 4; tn++) {
        int n0 = tn * 8 + 2 * (lane & 3);
        #pragma unroll
        for (int half = 0; half < 2; half++) {
            int node = m_base + 16 * wid + (lane >> 2) + 8 * half;
            if (node < N_NODES) {
                float va = acc[tn][2 * half], vb = acc[tn][2 * half + 1];
                #pragma unroll
                for (int p = 0; p < 2; p++) {
                    int nn = n0 + p;
                    float v = p ? vb : va;
                    if (nn < OUT_DIM) {
                        g_u2[(size_t)node * 16 + nn] = v;
                    } else if (nn < 2 * OUT_DIM) {
                        g_v2[(size_t)node * 16 + (nn - OUT_DIM)] = v + __ldg(&b2[nn - OUT_DIM]);
                    } else if (nn < 29) {
                        g_u2[(size_t)node * 16 + (nn - OUT_DIM)] = 0.f;  // u2 pads 13..15
                    }
                }
            }
        }
    }
}

// ---------------- final: out = hiermax(sigmoid(mean(u2[nbrs]) + v2[n])) ----------------
// Gather: 4 edges per warp-iteration; 8 lanes per edge, float2 per lane.
__global__ void aggF_kernel(const int* __restrict__ R, float* __restrict__ out) {
    __shared__ float s[WPB_F][16];
    int w = threadIdx.x >> 5, lane = threadIdx.x & 31;
    int n = blockIdx.x * WPB_F + w;
    if (n >= N_NODES) return;

    int beg = g_idx[n], end = g_idx[n + 1];
    int grp = lane >> 3;      // edge offset 0..3
    int fp  = lane & 7;       // feature pair
    float2 acc = make_float2(0.f, 0.f);
    #pragma unroll 2
    for (int e = beg; e < end; e += 4) {
        int ee = e + grp;
        if (ee < end) {
            int src = g_csr_src[ee];
            float2 v = *(const float2*)&g_u2[(size_t)src * 16 + 2 * fp];
            acc.x += v.x; acc.y += v.y;
        }
    }
    acc.x += __shfl_xor_sync(0xffffffffu, acc.x, 8);
    acc.y += __shfl_xor_sync(0xffffffffu, acc.y, 8);
    acc.x += __shfl_xor_sync(0xffffffffu, acc.x, 16);
    acc.y += __shfl_xor_sync(0xffffffffu, acc.y, 16);

    int degn = end - beg;
    float inv = 1.f / (float)(degn > 0 ? degn : 1);
    if (lane < 8) {
        int f0 = 2 * lane, f1 = f0 + 1;
        if (f0 < OUT_DIM) {
            float z = acc.x * inv + g_v2[(size_t)n * 16 + f0];
            s[w][f0] = 1.f / (1.f + expf(-z));
        }
        if (f1 < OUT_DIM) {
            float z = acc.y * inv + g_v2[(size_t)n * 16 + f1];
            s[w][f1] = 1.f / (1.f + expf(-z));
        }
    }
    __syncwarp();
    if (lane < OUT_DIM) {
        float mx = 0.f;
        #pragma unroll
        for (int jj = 0; jj < OUT_DIM; jj++) {
            if (__ldg(&R[lane * OUT_DIM + jj])) mx = fmaxf(mx, s[w][jj]);
        }
        out[(size_t)n * OUT_DIM + lane] = mx;
    }
}

// ---------------- launch ----------------
extern "C" void kernel_launch(void* const* d_in, const int* in_sizes, int n_in,
                              void* d_out, int out_size) {
    const float* x   = (const float*)d_in[0];
    const float* Wl0 = (const float*)d_in[1];
    const float* Wr0 = (const float*)d_in[2];
    const float* b0  = (const float*)d_in[3];
    const float* Wl1 = (const float*)d_in[4];
    const float* Wr1 = (const float*)d_in[5];
    const float* b1  = (const float*)d_in[6];
    const float* Wl2 = (const float*)d_in[7];
    const float* Wr2 = (const float*)d_in[8];
    const float* b2  = (const float*)d_in[9];
    const int*   ei  = (const int*)d_in[10];
    const int*   R   = (const int*)d_in[11];
    float* out = (float*)d_out;
    (void)in_sizes; (void)n_in; (void)out_size;

    prepw_kernel<<<72, 256>>>(Wl1, Wr1, Wl2, Wr2);                 // launch 1
    csr_coop_kernel<<<GRID_C, 256>>>(ei);                          // launch 2

    int nb = (N_NODES + WPB - 1) / WPB;
    layer0_kernel<<<nb, WPB * 32>>>(x, Wl0, Wr0, b0);              // launch 3

    dim3 gg((N_NODES + 63) / 64, 2);
    sgemm_tc_kernel<<<gg, 256>>>(b1);                              // launch 4 <- profiled

    int nbf = (N_NODES + WPB_F - 1) / WPB_F;
    agg2_kernel<<<nbf, WPB_F * 32>>>();                            // launch 5
    gemm2_tc_kernel<<<(N_NODES + 63) / 64, 128>>>(b2);             // launch 6
    aggF_kernel<<<nbf, WPB_F * 32>>>(R, out);                      // launch 7
}